// round 11
// baseline (speedup 1.0000x reference)
#include <cuda_runtime.h>
#include <cstdint>

// out[n, :] = weight[idx_n, :] where one_hot[n, idx_n] == 1.0
// N = 8192, VOCAB = 8192, D = 1024, fp32.
//
// Drain-free design: work item = (row, 4KB chunk). 65536 tasks statically
// striped over 7104 persistent warps in pass order (all chunk-0s first, ...).
// A per-row flag (zeroed by a tiny pre-kernel each launch) skips chunks of
// rows whose one-hot was already found, preserving the early-exit traffic
// floor. Correctness never depends on the flag: chunks past the one-hot are
// all zeros, so a stale flag only wastes bandwidth. The unique finder warp
// copies weight[idx] -> out[row].

#define N_ROWS  8192
#define VOCAB   8192
#define DIM     1024
#define CHUNK_FLOATS 1024                       // 4KB chunk
#define CHUNKS_PER_ROW (VOCAB / CHUNK_FLOATS)   // 8
#define N_TASKS (N_ROWS * CHUNKS_PER_ROW)       // 65536
#define THREADS 256
#define GRID    888                             // 148 SMs * 6 blocks
#define NWARPS  ((GRID * THREADS) / 32)         // 7104

__device__ unsigned int g_flag[N_ROWS];

__global__ void zero_flags_kernel() {
    int i = blockIdx.x * blockDim.x + threadIdx.x;
    if (i < N_ROWS) g_flag[i] = 0u;
}

__device__ __forceinline__ unsigned nz4(uint4 v) {
    return (unsigned)(v.x != 0u)
         | ((unsigned)(v.y != 0u) << 1)
         | ((unsigned)(v.z != 0u) << 2)
         | ((unsigned)(v.w != 0u) << 3);
}

__global__ __launch_bounds__(THREADS) void onehot_gather_kernel(
    const float* __restrict__ one_hot,
    const float* __restrict__ weight,
    float* __restrict__ out)
{
    const int lane = threadIdx.x & 31;
    const int warp = (int)((blockIdx.x * THREADS + threadIdx.x) >> 5);
    const unsigned FULL = 0xFFFFFFFFu;

    #pragma unroll 1
    for (int t = warp; t < N_TASKS; t += NWARPS) {
        const int r = t & (N_ROWS - 1);       // row
        const int c = t >> 13;                // chunk (pass) index, 0..7

        // skip hint: has this row's one-hot already been found?
        unsigned found = *(volatile unsigned*)&g_flag[r];
        if (found) continue;

        const uint4* __restrict__ chunk =
            reinterpret_cast<const uint4*>(one_hot)
            + (size_t)r * (VOCAB / 4) + c * (CHUNK_FLOATS / 4);

        // 8x uint4 per lane = 4KB, reduced immediately to a 32-bit nz mask
        unsigned nzm = 0;
        #pragma unroll
        for (int j = 0; j < 8; j++) {
            uint4 v = __ldcs(chunk + j * 32 + lane);
            nzm |= nz4(v) << (j * 4);
        }

        unsigned m = __ballot_sync(FULL, nzm != 0u);
        if (m) {
            int src = __ffs(m) - 1;
            int my_idx = -1;
            if (nzm) {
                int b = __ffs(nzm) - 1;
                int j = b >> 2, e = b & 3;
                my_idx = c * CHUNK_FLOATS + (j * 32 + lane) * 4 + e;
            }
            int idx = __shfl_sync(FULL, my_idx, src);

            if (lane == 0)
                *(volatile unsigned*)&g_flag[r] = 1u;   // skip hint for later passes

            // unique finder copies weight[idx, :] (4KB) -> out[r, :]
            const float4* __restrict__ wrow =
                reinterpret_cast<const float4*>(weight + (size_t)idx * DIM);
            float4* __restrict__ orow =
                reinterpret_cast<float4*>(out + (size_t)r * DIM);
            #pragma unroll
            for (int i = 0; i < DIM / 4 / 32; i++)      // 8 iterations
                orow[i * 32 + lane] = wrow[i * 32 + lane];
        }
    }
}

extern "C" void kernel_launch(void* const* d_in, const int* in_sizes, int n_in,
                              void* d_out, int out_size)
{
    const float* one_hot = (const float*)d_in[0];  // [N, VOCAB] fp32
    const float* weight  = (const float*)d_in[1];  // [VOCAB, D] fp32
    float* out = (float*)d_out;                    // [N, D] fp32

    zero_flags_kernel<<<N_ROWS / 256, 256>>>();
    onehot_gather_kernel<<<GRID, THREADS>>>(one_hot, weight, out);
}

// round 12
// speedup vs baseline: 1.2282x; 1.2282x over previous
#include <cuda_runtime.h>
#include <cstdint>

// out[n, :] = weight[idx_n, :] where one_hot[n, idx_n] == 1.0
// N = 8192, VOCAB = 8192, D = 1024, fp32.
//
// Two-phase split:
//   Phase 1 (scan): warp-per-row early-exit scan of one_hot (2KB rounds,
//       streaming loads). The finder lane writes idx[row] (4B). Pure read
//       stream -> no gather/write interference.
//   Phase 2 (gather): warp-per-row copy weight[idx[row]] -> out[row].
//       Pure copy, no dependent ballot chains; weight repeats hit L2;
//       out written with streaming stores.

#define N_ROWS  8192
#define VOCAB   8192
#define DIM     1024
#define WARPS_PER_BLOCK 8
#define THREADS (WARPS_PER_BLOCK * 32)
#define GRID    (N_ROWS / WARPS_PER_BLOCK)    // 1024

__device__ int g_idx[N_ROWS];

// ---------------- Phase 1: find the one-hot position per row ----------------
__global__ __launch_bounds__(THREADS) void scan_kernel(
    const float* __restrict__ one_hot)
{
    const int warp_global = (blockIdx.x * blockDim.x + threadIdx.x) >> 5;
    const int lane = threadIdx.x & 31;
    const unsigned FULL = 0xFFFFFFFFu;

    const uint4* __restrict__ row =
        reinterpret_cast<const uint4*>(one_hot + (size_t)warp_global * VOCAB);

    // 4x uint4 per lane = 2KB per round, 16 rounds max.
    #pragma unroll 1
    for (int base = 0; base < VOCAB / 4; base += 128) {
        uint4 v0 = __ldcs(row + base       + lane);
        uint4 v1 = __ldcs(row + base + 32  + lane);
        uint4 v2 = __ldcs(row + base + 64  + lane);
        uint4 v3 = __ldcs(row + base + 96  + lane);

        unsigned nz0 = (v0.x | v0.y | v0.z | v0.w);
        unsigned nz1 = (v1.x | v1.y | v1.z | v1.w);
        unsigned nz2 = (v2.x | v2.y | v2.z | v2.w);
        unsigned nz3 = (v3.x | v3.y | v3.z | v3.w);

        if (__ballot_sync(FULL, (nz0 | nz1 | nz2 | nz3) != 0u)) {
            // exactly one lane holds the hot element; only it writes
            uint4 v; int chunk;
            if      (nz0) { v = v0; chunk = 0; }
            else if (nz1) { v = v1; chunk = 1; }
            else if (nz2) { v = v2; chunk = 2; }
            else          { v = v3; chunk = 3; }
            if (nz0 | nz1 | nz2 | nz3) {
                int e = (v.x != 0u) ? 0 : (v.y != 0u) ? 1 : (v.z != 0u) ? 2 : 3;
                g_idx[warp_global] = (base + chunk * 32 + lane) * 4 + e;
            }
            break;
        }
    }
}

// ---------------- Phase 2: gather weight rows into out ----------------
__global__ __launch_bounds__(THREADS) void gather_kernel(
    const float* __restrict__ weight,
    float* __restrict__ out)
{
    const int warp_global = (blockIdx.x * blockDim.x + threadIdx.x) >> 5;
    const int lane = threadIdx.x & 31;
    const unsigned FULL = 0xFFFFFFFFu;

    int idx = 0;
    if (lane == 0) idx = g_idx[warp_global];
    idx = __shfl_sync(FULL, idx, 0);

    const float4* __restrict__ wrow =
        reinterpret_cast<const float4*>(weight + (size_t)idx * DIM);
    float4* __restrict__ orow =
        reinterpret_cast<float4*>(out + (size_t)warp_global * DIM);

    #pragma unroll
    for (int i = 0; i < DIM / 4 / 32; i++) {       // 8 iterations, 4KB
        float4 v = __ldg(wrow + i * 32 + lane);
        __stcs(orow + i * 32 + lane, v);
    }
}

extern "C" void kernel_launch(void* const* d_in, const int* in_sizes, int n_in,
                              void* d_out, int out_size)
{
    const float* one_hot = (const float*)d_in[0];  // [N, VOCAB] fp32
    const float* weight  = (const float*)d_in[1];  // [VOCAB, D] fp32
    float* out = (float*)d_out;                    // [N, D] fp32

    scan_kernel<<<GRID, THREADS>>>(one_hot);
    gather_kernel<<<GRID, THREADS>>>(weight, out);
}